// round 16
// baseline (speedup 1.0000x reference)
#include <cuda_runtime.h>
#include <cuda_bf16.h>
#include <cstdint>
#include <cstddef>

#define BATCH 8
#define NPTS  4096
#define CCH   128
#define HOUT  256
#define KNNK  16
#define ROWS  (BATCH * NPTS)

// ---------------- scratch (static __device__ — no runtime allocation) ----------------
__device__ float g_asrc[ROWS * CCH];
__device__ float g_adst[ROWS * CCH];
__device__ float g_val [ROWS * CCH];
__device__ int   g_knn [ROWS * KNNK];
// bf16 two-way splits
__device__ __nv_bfloat16 g_xh[ROWS * CCH], g_xl[ROWS * CCH];
__device__ __nv_bfloat16 g_ah[ROWS * CCH], g_al[ROWS * CCH];   // written by attn (fused split)
__device__ __nv_bfloat16 g_wht[3 * CCH * CCH], g_wlt[3 * CCH * CCH];   // [n][k]
__device__ __nv_bfloat16 g_woht[HOUT * CCH], g_wolt[HOUT * CCH];       // [n][k]

// ---------------- bf16 split helper ----------------
__device__ __forceinline__ void split_one(float v, __nv_bfloat16* h, __nv_bfloat16* l) {
    __nv_bfloat16 hi = __float2bfloat16(v);
    *h = hi;
    *l = __float2bfloat16(v - __bfloat162float(hi));
}

__global__ __launch_bounds__(256) void split_x_kernel(const float* __restrict__ x) {
    int i = blockIdx.x * 256 + threadIdx.x;
    split_one(x[i], &g_xh[i], &g_xl[i]);
}
// transpose-split W: src [128 k][N n] fp32 -> dst [N][128] bf16 (h, l)
__global__ __launch_bounds__(256) void split_w_kernel(const float* __restrict__ s0,
                                                      const float* __restrict__ s1,
                                                      const float* __restrict__ s2,
                                                      const float* __restrict__ s3) {
    int w = blockIdx.y;
    const float* src = (w == 0) ? s0 : (w == 1) ? s1 : (w == 2) ? s2 : s3;
    int N = (w < 3) ? CCH : HOUT;
    __nv_bfloat16* h = (w < 3) ? g_wht + w * CCH * CCH : g_woht;
    __nv_bfloat16* l = (w < 3) ? g_wlt + w * CCH * CCH : g_wolt;
    int i = blockIdx.x * 256 + threadIdx.x;
    if (i < CCH * N) {
        int k = i / N, n = i % N;
        split_one(src[i], &h[n * CCH + k], &l[n * CCH + k]);
    }
}

// ---------------- HMMA GEMM body (pointer-based smem; R13-identical math) ------------
#define AST 40   // padded bf16 stride for 32-wide k-chunk rows

__device__ __forceinline__ void hmma(float* c, const uint32_t* a, const uint32_t* b) {
    asm volatile(
        "mma.sync.aligned.m16n8k16.row.col.f32.bf16.bf16.f32 "
        "{%0,%1,%2,%3}, {%4,%5,%6,%7}, {%8,%9}, {%0,%1,%2,%3};"
        : "+f"(c[0]), "+f"(c[1]), "+f"(c[2]), "+f"(c[3])
        : "r"(a[0]), "r"(a[1]), "r"(a[2]), "r"(a[3]), "r"(b[0]), "r"(b[1]));
}

__device__ __forceinline__ void stage_tile(const __nv_bfloat16* __restrict__ g,
                                           int row0, int k0, int rows,
                                           __nv_bfloat16* dst) {
    for (int u = threadIdx.x; u < rows * 4; u += 256) {
        int row = u >> 2, seg = u & 3;
        uint4 v = *reinterpret_cast<const uint4*>(
            g + (size_t)(row0 + row) * CCH + k0 + seg * 8);
        *reinterpret_cast<uint4*>(dst + row * AST + seg * 8) = v;
    }
}

__device__ __forceinline__ uint32_t lds32(const __nv_bfloat16* p) {
    return *reinterpret_cast<const uint32_t*>(p);
}

__device__ __forceinline__ void gemm_mma_body(char* smem,
                                              const __nv_bfloat16* __restrict__ Ah,
                                              const __nv_bfloat16* __restrict__ Al,
                                              const __nv_bfloat16* __restrict__ Wh,
                                              const __nv_bfloat16* __restrict__ Wl,
                                              const float* __restrict__ bias,
                                              float* __restrict__ C, int NTOT,
                                              int m0, int n0) {
    __nv_bfloat16* sAh = reinterpret_cast<__nv_bfloat16*>(smem);            // 10240 B
    __nv_bfloat16* sAl = reinterpret_cast<__nv_bfloat16*>(smem + 10240);    // 10240 B
    __nv_bfloat16* sWh = reinterpret_cast<__nv_bfloat16*>(smem + 20480);    //  5120 B
    __nv_bfloat16* sWl = reinterpret_cast<__nv_bfloat16*>(smem + 25600);    //  5120 B

    int tid = threadIdx.x, wid = tid >> 5, lane = tid & 31;
    int wm = (wid & 3) * 32;
    int wn = (wid >> 2) * 32;
    int r  = lane >> 2;
    int cq = (lane & 3) * 2;

    float acc[2][4][4];
#pragma unroll
    for (int i = 0; i < 2; i++)
#pragma unroll
        for (int j = 0; j < 4; j++)
#pragma unroll
            for (int q = 0; q < 4; q++) acc[i][j][q] = 0.f;

    for (int kc = 0; kc < 4; kc++) {
        int k0 = kc * 32;
        stage_tile(Ah, m0, k0, 128, sAh);
        stage_tile(Al, m0, k0, 128, sAl);
        stage_tile(Wh, n0, k0, 64,  sWh);
        stage_tile(Wl, n0, k0, 64,  sWl);
        __syncthreads();

#pragma unroll
        for (int ks = 0; ks < 2; ks++) {
            int kk = ks * 16;
            uint32_t fah[2][4], fal[2][4];
#pragma unroll
            for (int tm = 0; tm < 2; tm++) {
                const __nv_bfloat16* base = sAh + (wm + tm * 16 + r) * AST + kk + cq;
                const __nv_bfloat16* basl = sAl + (wm + tm * 16 + r) * AST + kk + cq;
                fah[tm][0] = lds32(base);
                fah[tm][1] = lds32(base + 8 * AST);
                fah[tm][2] = lds32(base + 8);
                fah[tm][3] = lds32(base + 8 * AST + 8);
                fal[tm][0] = lds32(basl);
                fal[tm][1] = lds32(basl + 8 * AST);
                fal[tm][2] = lds32(basl + 8);
                fal[tm][3] = lds32(basl + 8 * AST + 8);
            }
            uint32_t fbh[4][2], fbl[4][2];
#pragma unroll
            for (int tn = 0; tn < 4; tn++) {
                const __nv_bfloat16* base = sWh + (wn + tn * 8 + r) * AST + kk + cq;
                const __nv_bfloat16* basl = sWl + (wn + tn * 8 + r) * AST + kk + cq;
                fbh[tn][0] = lds32(base);
                fbh[tn][1] = lds32(base + 8);
                fbl[tn][0] = lds32(basl);
                fbl[tn][1] = lds32(basl + 8);
            }
#pragma unroll
            for (int tm = 0; tm < 2; tm++)
#pragma unroll
                for (int tn = 0; tn < 4; tn++) {
                    hmma(acc[tm][tn], fah[tm], fbh[tn]);
                    hmma(acc[tm][tn], fah[tm], fbl[tn]);
                    hmma(acc[tm][tn], fal[tm], fbh[tn]);
                }
        }
        __syncthreads();
    }

#pragma unroll
    for (int tm = 0; tm < 2; tm++)
#pragma unroll
        for (int tn = 0; tn < 4; tn++) {
            int m = m0 + wm + tm * 16 + r;
            int n = n0 + wn + tn * 8 + cq;
            float bv0 = 0.f, bv1 = 0.f;
            if (bias) { bv0 = bias[n]; bv1 = bias[n + 1]; }
            float2 lo = make_float2(acc[tm][tn][0] + bv0, acc[tm][tn][1] + bv1);
            float2 hi = make_float2(acc[tm][tn][2] + bv0, acc[tm][tn][3] + bv1);
            *reinterpret_cast<float2*>(C + (size_t)m * NTOT + n) = lo;
            *reinterpret_cast<float2*>(C + (size_t)(m + 8) * NTOT + n) = hi;
        }
}

// ---------------- KNN body (R10/R14 measured-best form; pointer-based smem) ----------
__device__ __forceinline__ void knn_body(char* smem, const float* __restrict__ pos,
                                         int kb) {
    float2* sxy = reinterpret_cast<float2*>(smem);            // 32 KB
    float*  szv = reinterpret_cast<float*>(smem + 32768);     // 16 KB

    const int bpb = NPTS / 32;
    int b  = kb / bpb;
    int rb = kb % bpb;
    const float* pb = pos + (size_t)b * NPTS * 3;

    for (int t = threadIdx.x; t < NPTS; t += 256) {
        const float* p = pb + t * 3;
        sxy[t] = make_float2(p[0], p[1]);
        szv[t] = p[2];
    }
    __syncthreads();

    int warp = threadIdx.x >> 5;
    int lane = threadIdx.x & 31;
    const unsigned FULL = 0xffffffffu;
    int i0 = rb * 32 + warp * 4;

    float3 pi[4];
    unsigned long long cur[4], tk[4];
    float th[4];
#pragma unroll
    for (int r = 0; r < 4; r++) {
        float2 q = sxy[i0 + r];
        pi[r] = make_float3(q.x, q.y, szv[i0 + r]);
        cur[r] = ~0ull;
        tk[r]  = ~0ull;
        th[r]  = __int_as_float(0x7f800000);
    }

    for (int j0 = 0; j0 < NPTS; j0 += 32) {
        int j = j0 + lane;
        float2 pj = sxy[j];
        float  zj = szv[j];
#pragma unroll
        for (int r = 0; r < 4; r++) {
            float dx = pi[r].x - pj.x;
            float dy = pi[r].y - pj.y;
            float dz = pi[r].z - zj;
            float d2 = fmaf(dx, dx, fmaf(dy, dy, dz * dz));

            unsigned mask = __ballot_sync(FULL, d2 <= th[r]);
            if (mask) {
                unsigned long long key =
                    ((unsigned long long)__float_as_uint(d2) << 32) | (unsigned)j;
                bool changed = false;
                while (mask) {
                    int src = __ffs(mask) - 1;
                    mask &= mask - 1;
                    unsigned long long cand = __shfl_sync(FULL, key, src);
                    if (cand < tk[r]) {
                        unsigned long long prev = __shfl_up_sync(FULL, cur[r], 1);
                        bool bigger = cur[r] > cand;
                        unsigned long long ins =
                            (lane > 0 && prev > cand) ? prev : cand;
                        cur[r] = bigger ? ins : cur[r];
                        changed = true;
                    }
                }
                if (changed) {
                    tk[r] = __shfl_sync(FULL, cur[r], 15);
                    th[r] = __uint_as_float((unsigned)(tk[r] >> 32));
                }
            }
        }
    }

    if (lane < KNNK) {
#pragma unroll
        for (int r = 0; r < 4; r++)
            g_knn[((size_t)b * NPTS + i0 + r) * KNNK + lane] =
                (int)(unsigned)(cur[r] & 0xffffffffu);
    }
}

// ---------------- fused launch: gemm_in blocks [0,1536) + knn blocks [1536,2560) ------
#define GEMM_IN_BLOCKS 1536   // 256 m-tiles x 2 n-tiles x 3 weights
#define KNN_BLOCKS     1024

__global__ __launch_bounds__(256, 3) void fused_in_kernel(const float* __restrict__ pos) {
    __shared__ __align__(16) char smem_u[49152];   // union: gemm 30.7KB / knn 48KB
    int gb = blockIdx.x;
    if (gb < GEMM_IN_BLOCKS) {
        int mb = gb & 255;
        int nb = (gb >> 8) & 1;
        int z  = gb >> 9;
        const __nv_bfloat16* wh = g_wht + z * CCH * CCH;
        const __nv_bfloat16* wl = g_wlt + z * CCH * CCH;
        float* C = (z == 0) ? g_asrc : (z == 1) ? g_adst : g_val;
        gemm_mma_body(smem_u, g_xh, g_xl, wh, wl, nullptr, C, CCH, mb * 128, nb * 64);
    } else {
        knn_body(smem_u, pos, gb - GEMM_IN_BLOCKS);
    }
}

// ---------------- gemm_out (standalone, R13-identical) ----------------
__global__ __launch_bounds__(256) void gemm_mma_out_kernel(const float* __restrict__ bout,
                                                           float* __restrict__ out) {
    __shared__ __align__(16) char smem_u[30720];
    gemm_mma_body(smem_u, g_ah, g_al, g_woht, g_wolt, bout, out, HOUT,
                  blockIdx.x * 128, blockIdx.y * 64);
}

// ---------------- attention + fused bf16 split of the result ----------------
__global__ __launch_bounds__(128) void attn_kernel(const float* __restrict__ pos,
                                                   const float* __restrict__ Wpos,
                                                   const float* __restrict__ bpos) {
    int row = blockIdx.x;
    int b   = row >> 12;
    int i   = row & (NPTS - 1);
    int c   = threadIdx.x;

    __shared__ float srel[KNNK][3];
    __shared__ int   sj[KNNK];

    if (c < KNNK) {
        int j = g_knn[(size_t)row * KNNK + c];
        sj[c] = j;
        const float* pb = pos + (size_t)b * NPTS * 3;
        srel[c][0] = pb[i * 3 + 0] - pb[j * 3 + 0];
        srel[c][1] = pb[i * 3 + 1] - pb[j * 3 + 1];
        srel[c][2] = pb[i * 3 + 2] - pb[j * 3 + 2];
    }
    __syncthreads();

    float w0 = Wpos[c];
    float w1 = Wpos[CCH + c];
    float w2 = Wpos[2 * CCH + c];
    float bp = bpos[c];
    float ad = g_adst[(size_t)row * CCH + c];

    float alpha[KNNK], vd[KNNK];
    float mx = -3.4e38f;
#pragma unroll
    for (int k = 0; k < KNNK; k++) {
        int j = sj[k];
        size_t base = ((size_t)b * NPTS + j) * CCH + c;
        float as = g_asrc[base];
        float vv = g_val[base];
        float dl = fmaf(srel[k][0], w0, fmaf(srel[k][1], w1, fmaf(srel[k][2], w2, bp)));
        alpha[k] = (ad - as) + dl;
        vd[k]    = vv + dl;
        mx = fmaxf(mx, alpha[k]);
    }
    float s = 0.f, accv = 0.f;
#pragma unroll
    for (int k = 0; k < KNNK; k++) {
        float e = __expf(alpha[k] - mx);
        s += e;
        accv = fmaf(e, vd[k], accv);
    }
    float v = accv / s;
    size_t o = (size_t)row * CCH + c;
    split_one(v, &g_ah[o], &g_al[o]);
}

// ---------------- launch (kernel launches ONLY — graph-capture safe) ----------------
extern "C" void kernel_launch(void* const* d_in, const int* in_sizes, int n_in,
                              void* d_out, int out_size) {
    const float* x    = (const float*)d_in[0];
    const float* pos  = (const float*)d_in[1];
    const float* Wsrc = (const float*)d_in[2];
    const float* Wdst = (const float*)d_in[3];
    const float* Wval = (const float*)d_in[4];
    const float* Wpos = (const float*)d_in[5];
    const float* bpos = (const float*)d_in[6];
    const float* Wout = (const float*)d_in[7];
    const float* bout = (const float*)d_in[8];
    float* out = (float*)d_out;

    split_x_kernel<<<ROWS * CCH / 256, 256>>>(x);                               // 1
    split_w_kernel<<<dim3(CCH * HOUT / 256, 4), 256>>>(Wsrc, Wdst, Wval, Wout); // 2
    fused_in_kernel<<<GEMM_IN_BLOCKS + KNN_BLOCKS, 256>>>(pos);                 // 3 knn || gemm_in
    attn_kernel<<<ROWS, 128>>>(pos, Wpos, bpos);                                // 4
    gemm_mma_out_kernel<<<dim3(ROWS / 128, HOUT / 64), 256>>>(bout, out);       // 5
}